// round 5
// baseline (speedup 1.0000x reference)
#include <cuda_runtime.h>

// Problem constants
#define NB 8
#define NC 256
#define NH 64
#define NW 64
#define NRED 64
#define NKK 9

// Scratch (device globals: allocation-free rule)
__device__ float g_x1[NB * NC * NH * NW];     // 32 MB: output of dwconv_in
__device__ float g_kern[NB * NKK * NH * NW];  // 1.125 MB: per-pixel 3x3 kernels

// ---------------------------------------------------------------------------
// Packed fp32x2 helpers (sm_103a)
// ---------------------------------------------------------------------------
__device__ __forceinline__ unsigned long long pack2(float v) {
    unsigned long long r;
    unsigned u = __float_as_uint(v);
    asm("mov.b64 %0, {%1, %1};" : "=l"(r) : "r"(u));
    return r;
}
__device__ __forceinline__ void fma2(unsigned long long& d,
                                     unsigned long long a,
                                     unsigned long long b) {
    asm("fma.rn.f32x2 %0, %1, %2, %0;" : "+l"(d) : "l"(a), "l"(b));
}

// ---------------------------------------------------------------------------
// Kernel A: fused dwconv_in + reduce(256->64) + relu + span(64->9)
// Tile: 32 wide x 8 tall, 256 threads, grid (2, 8, 8) = 128 blocks.
// ---------------------------------------------------------------------------
#define A_TW 32
#define A_TH 8
#define A_HW 34
#define A_HH 10
#define A_HSZ (A_HW * A_HH)   // 340
#define A_CPC 8               // channels per group

#define A_WT_STRIDE 68
#define A_OFF_WT  0                                  // 256*68 = 17408 (reused as s_r[64][256])
#define A_OFF_X   17408                              // 8*340 = 2720
#define A_OFF_X1  (A_OFF_X + A_CPC * A_HSZ)          // 20128 (16B aligned), 8*256
#define A_OFF_WIN (A_OFF_X1 + A_CPC * 256)           // 22176, 2304
#define A_OFF_BIN (A_OFF_WIN + 2304)                 // 24480, 256
#define A_OFF_WSP (A_OFF_BIN + 256)                  // 24736, 576
#define A_OFF_BSP (A_OFF_WSP + 576)                  // 25312, 16
#define A_OFF_BRD (A_OFF_BSP + 16)                   // 25328, 64
#define A_SMEM_FLOATS (A_OFF_BRD + 64)               // 25392
#define A_SMEM_BYTES (A_SMEM_FLOATS * 4)             // 101568

__global__ __launch_bounds__(256, 1)
void tm_kernelA(const float* __restrict__ x,
                const float* __restrict__ w_in, const float* __restrict__ b_in,
                const float* __restrict__ w_red, const float* __restrict__ b_red,
                const float* __restrict__ w_span, const float* __restrict__ b_span)
{
    extern __shared__ float sm[];
    const int tid = threadIdx.x;
    const int b  = blockIdx.z;
    const int y0 = blockIdx.y * A_TH;
    const int x0 = blockIdx.x * A_TW;

    // ---- stage weights into smem ----
    for (int i = tid; i < NRED * NC; i += 256) {
        int j = i >> 8, c = i & 255;                 // w_red[j][c]
        sm[A_OFF_WT + c * A_WT_STRIDE + j] = w_red[i];
    }
    for (int i = tid; i < NC * 9; i += 256) sm[A_OFF_WIN + i] = w_in[i];
    if (tid < NC)   sm[A_OFF_BIN + tid] = b_in[tid];
    for (int i = tid; i < NKK * NRED; i += 256) sm[A_OFF_WSP + i] = w_span[i];
    if (tid < NKK)  sm[A_OFF_BSP + tid] = b_span[tid];
    if (tid < NRED) sm[A_OFF_BRD + tid] = b_red[tid];
    __syncthreads();

    const int py = tid >> 5;          // 0..7  (also tj: j-group)
    const int px = tid & 31;          // 0..31 (also tp: pixel-group)
    const int tj = py, tp = px;

    // f32x2 accumulators: 8 j-values x 4 pixel-pairs
    unsigned long long acc[8][4];
#pragma unroll
    for (int jj = 0; jj < 8; jj++)
#pragma unroll
        for (int q = 0; q < 4; q++) acc[jj][q] = 0ULL;

    for (int c0 = 0; c0 < NC; c0 += A_CPC) {
        // phase 1: halo load for 8 channels (zero-padded)
        for (int i = tid; i < A_CPC * A_HSZ; i += 256) {
            int cc = i / A_HSZ, e = i % A_HSZ;
            int r = e / A_HW, col = e % A_HW;
            int gy = y0 - 1 + r, gx = x0 - 1 + col;
            float v = 0.f;
            if (gy >= 0 && gy < NH && gx >= 0 && gx < NW)
                v = x[((b * NC + c0 + cc) * NH + gy) * NW + gx];
            sm[A_OFF_X + i] = v;
        }
        __syncthreads();

        // phase 2: depthwise 3x3 -> s_x1 + g_x1
#pragma unroll
        for (int cc = 0; cc < A_CPC; cc++) {
            const int c = c0 + cc;
            const float* wv = &sm[A_OFF_WIN + c * 9];
            const float* xs = &sm[A_OFF_X + cc * A_HSZ + py * A_HW + px];
            float v = sm[A_OFF_BIN + c];
#pragma unroll
            for (int di = 0; di < 3; di++)
#pragma unroll
                for (int dj = 0; dj < 3; dj++)
                    v = fmaf(wv[di * 3 + dj], xs[di * A_HW + dj], v);
            sm[A_OFF_X1 + cc * 256 + tid] = v;
            g_x1[((b * NC + c) * NH + y0 + py) * NW + x0 + px] = v;
        }
        __syncthreads();

        // phase 3: reduce-GEMM micro-steps (f32x2)
#pragma unroll
        for (int cc = 0; cc < A_CPC; cc++) {
            const int c = c0 + cc;
            const float* wr = &sm[A_OFF_WT + c * A_WT_STRIDE + tj * 8];
            unsigned long long wv[8];
#pragma unroll
            for (int jj = 0; jj < 8; jj++) wv[jj] = pack2(wr[jj]);
            const ulonglong2* xp =
                reinterpret_cast<const ulonglong2*>(&sm[A_OFF_X1 + cc * 256 + tp * 8]);
            ulonglong2 xa = xp[0], xb = xp[1];
            unsigned long long xv[4] = {xa.x, xa.y, xb.x, xb.y};
#pragma unroll
            for (int jj = 0; jj < 8; jj++)
#pragma unroll
                for (int q = 0; q < 4; q++)
                    fma2(acc[jj][q], wv[jj], xv[q]);
        }
        __syncthreads();   // also protects s_wT before the s_r overwrite below
    }

    // ---- r = relu(acc + b_red) staged into smem (reuse w_red region) ----
#pragma unroll
    for (int jj = 0; jj < 8; jj++) {
        const int j = tj * 8 + jj;
        const float bj = sm[A_OFF_BRD + j];
#pragma unroll
        for (int q = 0; q < 4; q++) {
            unsigned long long v = acc[jj][q];
            float lo = __uint_as_float((unsigned)(v & 0xffffffffu));
            float hi = __uint_as_float((unsigned)(v >> 32));
            lo = fmaxf(lo + bj, 0.f);
            hi = fmaxf(hi + bj, 0.f);
            sm[A_OFF_WT + j * 256 + tp * 8 + 2 * q]     = lo;
            sm[A_OFF_WT + j * 256 + tp * 8 + 2 * q + 1] = hi;
        }
    }
    __syncthreads();

    // ---- span: kern[k][p] = b_span[k] + sum_j w_span[k][j] * r[j][p] ----
    {
        float kf[NKK];
#pragma unroll
        for (int k = 0; k < NKK; k++) kf[k] = sm[A_OFF_BSP + k];
#pragma unroll 8
        for (int j = 0; j < NRED; j++) {
            float rv = sm[A_OFF_WT + j * 256 + tid];
#pragma unroll
            for (int k = 0; k < NKK; k++)
                kf[k] = fmaf(sm[A_OFF_WSP + k * NRED + j], rv, kf[k]);
        }
        const int gy = y0 + py, gx = x0 + px;
#pragma unroll
        for (int k = 0; k < NKK; k++)
            g_kern[((b * NKK + k) * NH + gy) * NW + gx] = kf[k];
    }
}

// ---------------------------------------------------------------------------
// Kernel B: fused involution + dwconv_out.
// Tile: 64 wide x 16 tall, 32 channels per block, grid (4, 8, 8) = 256 blocks.
// y is computed on an extended 18x68 tile in smem (never hits DRAM).
// ---------------------------------------------------------------------------
#define B_TH2 16
#define B_EH 18
#define B_EW 66          // meaningful ext cols; compute padded to 68
#define B_EWP 68         // padded ext stride (mult of 4)
#define B_ESZ (B_EH * B_EWP)      // 1224
#define B_HH2 20
#define B_HWP 72         // halo stride (mult of 4)
#define B_HSZ (B_HH2 * B_HWP)     // 1440

#define B_OFF_K  0                        // 9 * 1224 = 11016
#define B_OFF_XH 11016                    // 1440
#define B_OFF_Y  (B_OFF_XH + B_HSZ)       // 12456, 1224
#define B_OFF_WO (B_OFF_Y + B_ESZ)        // 13680, 288
#define B_OFF_BO (B_OFF_WO + 288)         // 13968, 32
#define B_SMEM_FLOATS (B_OFF_BO + 32)     // 14000
#define B_SMEM_BYTES (B_SMEM_FLOATS * 4)  // 56000

__global__ __launch_bounds__(256)
void tm_kernelB(const float* __restrict__ w_out, const float* __restrict__ b_out,
                float* __restrict__ out)
{
    extern __shared__ float sm[];
    const int tid = threadIdx.x;
    const int b   = blockIdx.z;
    const int cg0 = blockIdx.y * 32;
    const int y0  = blockIdx.x * B_TH2;

    // ---- stage kern on the extended tile (zero outside image) ----
    for (int i = tid; i < NKK * B_ESZ; i += 256) {
        int kk = i / B_ESZ, e = i % B_ESZ;
        int Ey = e / B_EWP, Ex = e % B_EWP;
        int gy = y0 - 1 + Ey, gx = Ex - 1;
        float v = 0.f;
        if (gy >= 0 && gy < NH && gx >= 0 && gx < NW)
            v = g_kern[((b * NKK + kk) * NH + gy) * NW + gx];
        sm[B_OFF_K + i] = v;
    }
    for (int i = tid; i < 32 * 9; i += 256) sm[B_OFF_WO + i] = w_out[cg0 * 9 + i];
    if (tid < 32) sm[B_OFF_BO + tid] = b_out[cg0 + tid];
    __syncthreads();

    for (int ci = 0; ci < 32; ci++) {
        const int c = cg0 + ci;

        // phase 1: x1 halo (zero-padded), 20 rows x 72 cols
        for (int i = tid; i < B_HSZ; i += 256) {
            int r = i / B_HWP, cc = i % B_HWP;
            int gy = y0 - 2 + r, gx = cc - 2;
            float v = 0.f;
            if (gy >= 0 && gy < NH && gx >= 0 && gx < NW)
                v = g_x1[((b * NC + c) * NH + gy) * NW + gx];
            sm[B_OFF_XH + i] = v;
        }
        __syncthreads();

        // phase 2: involution on extended tile, float4-vectorized
        // items: 18 rows x 17 col-groups of 4 = 306
        for (int it = tid; it < B_EH * 17; it += 256) {
            int Ey = it / 17, Ex0 = (it % 17) * 4;
            float y4x = 0.f, y4y = 0.f, y4z = 0.f, y4w = 0.f;
#pragma unroll
            for (int ki = 0; ki < 3; ki++) {
                const float4 xa = *reinterpret_cast<const float4*>(
                    &sm[B_OFF_XH + (Ey + ki) * B_HWP + Ex0]);
                const float4 xb = *reinterpret_cast<const float4*>(
                    &sm[B_OFF_XH + (Ey + ki) * B_HWP + Ex0 + 4]);
                const float a[8] = {xa.x, xa.y, xa.z, xa.w, xb.x, xb.y, xb.z, xb.w};
#pragma unroll
                for (int kj = 0; kj < 3; kj++) {
                    const float4 kv = *reinterpret_cast<const float4*>(
                        &sm[B_OFF_K + (ki * 3 + kj) * B_ESZ + Ey * B_EWP + Ex0]);
                    y4x = fmaf(kv.x, a[kj + 0], y4x);
                    y4y = fmaf(kv.y, a[kj + 1], y4y);
                    y4z = fmaf(kv.z, a[kj + 2], y4z);
                    y4w = fmaf(kv.w, a[kj + 3], y4w);
                }
            }
            float4 st = {y4x, y4y, y4z, y4w};
            *reinterpret_cast<float4*>(&sm[B_OFF_Y + Ey * B_EWP + Ex0]) = st;
        }
        __syncthreads();

        // phase 3: depthwise 3x3 on y -> out, 4 px per thread (16 rows x 16 groups)
        {
            float wo[9];
#pragma unroll
            for (int k = 0; k < 9; k++) wo[k] = sm[B_OFF_WO + ci * 9 + k];
            const float bo = sm[B_OFF_BO + ci];
            const int Oy = tid >> 4;
            const int Ox0 = (tid & 15) * 4;
            float o0 = bo, o1 = bo, o2 = bo, o3 = bo;
#pragma unroll
            for (int di = 0; di < 3; di++) {
                const float4 ya = *reinterpret_cast<const float4*>(
                    &sm[B_OFF_Y + (Oy + di) * B_EWP + Ox0]);
                const float4 yb = *reinterpret_cast<const float4*>(
                    &sm[B_OFF_Y + (Oy + di) * B_EWP + Ox0 + 4]);
                const float a[8] = {ya.x, ya.y, ya.z, ya.w, yb.x, yb.y, yb.z, yb.w};
#pragma unroll
                for (int dj = 0; dj < 3; dj++) {
                    const float w = wo[di * 3 + dj];
                    o0 = fmaf(w, a[dj + 0], o0);
                    o1 = fmaf(w, a[dj + 1], o1);
                    o2 = fmaf(w, a[dj + 2], o2);
                    o3 = fmaf(w, a[dj + 3], o3);
                }
            }
            float4 st = {o0, o1, o2, o3};
            *reinterpret_cast<float4*>(
                &out[((b * NC + c) * NH + y0 + Oy) * NW + Ox0]) = st;
        }
        // next iteration's phase-1 sync separates phase3(c) reads of s_y
        // from phase2(c+1) writes; s_xh rewrites are fenced by the sync
        // after phase2(c).
    }
}

// ---------------------------------------------------------------------------
extern "C" void kernel_launch(void* const* d_in, const int* in_sizes, int n_in,
                              void* d_out, int out_size)
{
    (void)in_sizes; (void)n_in; (void)out_size;
    const float* x      = (const float*)d_in[0];
    const float* w_in   = (const float*)d_in[1];
    const float* b_in   = (const float*)d_in[2];
    const float* w_red  = (const float*)d_in[3];
    const float* b_red  = (const float*)d_in[4];
    const float* w_span = (const float*)d_in[5];
    const float* b_span = (const float*)d_in[6];
    const float* w_out  = (const float*)d_in[7];
    const float* b_out  = (const float*)d_in[8];
    float* out = (float*)d_out;

    cudaFuncSetAttribute(tm_kernelA, cudaFuncAttributeMaxDynamicSharedMemorySize,
                         A_SMEM_BYTES);
    cudaFuncSetAttribute(tm_kernelB, cudaFuncAttributeMaxDynamicSharedMemorySize,
                         B_SMEM_BYTES);

    tm_kernelA<<<dim3(2, 8, 8), 256, A_SMEM_BYTES>>>(
        x, w_in, b_in, w_red, b_red, w_span, b_span);
    tm_kernelB<<<dim3(4, 8, 8), 256, B_SMEM_BYTES>>>(w_out, b_out, out);
}

// round 7
// speedup vs baseline: 2.1848x; 2.1848x over previous
#include <cuda_runtime.h>

// Problem constants
#define NB 8
#define NC 256
#define NH 64
#define NW 64
#define NRED 64
#define NKK 9
#define NPIX (NB * NH * NW)        // 32768 pixels (kern has no channel dim)

// Scratch (device globals: allocation-free rule)
__device__ float g_x1[NB * NC * NH * NW];     // 32 MB: output of dwconv_in
__device__ float g_kern[NB * NKK * NH * NW];  // 1.125 MB: per-pixel 3x3 kernels

// ---------------------------------------------------------------------------
// Packed fp32x2 helpers (sm_103a)
// ---------------------------------------------------------------------------
__device__ __forceinline__ unsigned long long pack2(float v) {
    unsigned long long r;
    unsigned u = __float_as_uint(v);
    asm("mov.b64 %0, {%1, %1};" : "=l"(r) : "r"(u));
    return r;
}
__device__ __forceinline__ void fma2(unsigned long long& d,
                                     unsigned long long a,
                                     unsigned long long b) {
    asm("fma.rn.f32x2 %0, %1, %2, %0;" : "+l"(d) : "l"(a), "l"(b));
}
__device__ __forceinline__ float lo32(unsigned long long v) {
    return __uint_as_float((unsigned)(v & 0xffffffffu));
}
__device__ __forceinline__ float hi32(unsigned long long v) {
    return __uint_as_float((unsigned)(v >> 32));
}

// ---------------------------------------------------------------------------
// Kernel A1: dwconv_in  (x -> g_x1). Tile 16h x 64w per (b,c). 8192 blocks.
// ---------------------------------------------------------------------------
#define A1_HW 68                 // halo stride (17 f4)
#define A1_HH 18
#define A1_HSZ (A1_HH * A1_HW)   // 1224

__global__ __launch_bounds__(256)
void tm_A1(const float* __restrict__ x,
           const float* __restrict__ w_in, const float* __restrict__ b_in)
{
    __shared__ float sh[A1_HSZ];
    const int tid = threadIdx.x;
    const int h0 = blockIdx.x * 16;
    const int c  = blockIdx.y;
    const int b  = blockIdx.z;

    const float* xc = x + (b * NC + c) * (NH * NW);
    for (int i = tid; i < A1_HSZ; i += 256) {
        int r = i / A1_HW, col = i - r * A1_HW;
        int gy = h0 - 1 + r, gx = col - 1;
        float v = 0.f;
        if (gy >= 0 && gy < NH && gx >= 0 && gx < NW) v = xc[gy * NW + gx];
        sh[i] = v;
    }
    float wv[9];
#pragma unroll
    for (int k = 0; k < 9; k++) wv[k] = __ldg(&w_in[c * 9 + k]);
    const float bias = __ldg(&b_in[c]);
    __syncthreads();

    const int Oy = tid >> 4;
    const int Ox0 = (tid & 15) * 4;
    float o0 = bias, o1 = bias, o2 = bias, o3 = bias;
#pragma unroll
    for (int di = 0; di < 3; di++) {
        const float4 xa = *reinterpret_cast<const float4*>(&sh[(Oy + di) * A1_HW + Ox0]);
        const float4 xb = *reinterpret_cast<const float4*>(&sh[(Oy + di) * A1_HW + Ox0 + 4]);
        const float a[8] = {xa.x, xa.y, xa.z, xa.w, xb.x, xb.y, xb.z, xb.w};
#pragma unroll
        for (int dj = 0; dj < 3; dj++) {
            const float w = wv[di * 3 + dj];
            o0 = fmaf(w, a[dj + 0], o0);
            o1 = fmaf(w, a[dj + 1], o1);
            o2 = fmaf(w, a[dj + 2], o2);
            o3 = fmaf(w, a[dj + 3], o3);
        }
    }
    float4 st = {o0, o1, o2, o3};
    *reinterpret_cast<float4*>(&g_x1[(b * NC + c) * (NH * NW) + (h0 + Oy) * NW + Ox0]) = st;
}

// ---------------------------------------------------------------------------
// Kernel A2: reduce GEMM (64x256x32768) + relu + span (9x64) -> g_kern.
// 512 blocks x 128 threads. Block tile: 64j x 64px, c chunked by 32.
// Thread: 8j x 4px, f32x2 accumulators. Pipelined gmem->smem chunk loads.
// ---------------------------------------------------------------------------
#define A2_SX 0                   // s_x[32c][64px] = 2048
#define A2_SW 2048                // s_w[32c][68]   = 2176 (stride 68 for 16B-aligned f4)
#define A2_SR 0                   // s_r[64j][64px] = 4096 (overlaps SX+SW after main loop)
#define A2_MAIN 4224
#define A2_AUX  A2_MAIN           // aux region after main
#define A2_WSP  (A2_AUX + 0)      // 576
#define A2_BSP  (A2_AUX + 576)    // 9 (pad to 16)
#define A2_BRD  (A2_AUX + 592)    // 64
#define A2_SMEM (A2_AUX + 656)    // 4880 floats = 19.5KB

__global__ __launch_bounds__(128)
void tm_A2(const float* __restrict__ w_red, const float* __restrict__ b_red,
           const float* __restrict__ w_span, const float* __restrict__ b_span)
{
    __shared__ float sm[A2_SMEM];
    const int tid = threadIdx.x;
    const int px0 = blockIdx.x * 64;
    const int b = px0 >> 12;
    const int pxin = px0 & 4095;

    // aux staging
    for (int i = tid; i < 656; i += 128) {
        if (i < 576)               sm[A2_AUX + i] = w_span[i];
        else if (i < 585)          sm[A2_AUX + i] = b_span[i - 576];
        else if (i >= 592)         sm[A2_AUX + i] = b_red[i - 592];
    }

    const int jg = tid >> 4;      // 0..7
    const int pxg = tid & 15;     // 0..15

    unsigned long long acc[8][2];
#pragma unroll
    for (int jj = 0; jj < 8; jj++) { acc[jj][0] = 0ULL; acc[jj][1] = 0ULL; }

    const float* x1base = g_x1 + (long long)b * NC * 4096 + pxin;

    float4 xr[4], wr[4];
    // prefetch chunk 0
    {
        const int c0c = 0;
#pragma unroll
        for (int k = 0; k < 4; k++) {
            int i = tid + k * 128;
            int cl = i >> 4, pq = i & 15;
            xr[k] = *reinterpret_cast<const float4*>(&x1base[(c0c + cl) * 4096 + pq * 4]);
            int j = i >> 3, cq = i & 7;
            wr[k] = *reinterpret_cast<const float4*>(&w_red[j * NC + c0c + cq * 4]);
        }
    }

    for (int ch = 0; ch < 8; ch++) {
        // store staged chunk
#pragma unroll
        for (int k = 0; k < 4; k++) {
            int i = tid + k * 128;
            int cl = i >> 4, pq = i & 15;
            *reinterpret_cast<float4*>(&sm[A2_SX + cl * 64 + pq * 4]) = xr[k];
            int j = i >> 3, cq = i & 7;
            sm[A2_SW + (cq * 4 + 0) * 68 + j] = wr[k].x;
            sm[A2_SW + (cq * 4 + 1) * 68 + j] = wr[k].y;
            sm[A2_SW + (cq * 4 + 2) * 68 + j] = wr[k].z;
            sm[A2_SW + (cq * 4 + 3) * 68 + j] = wr[k].w;
        }
        __syncthreads();

        if (ch + 1 < 8) {
            const int c0c = (ch + 1) * 32;
#pragma unroll
            for (int k = 0; k < 4; k++) {
                int i = tid + k * 128;
                int cl = i >> 4, pq = i & 15;
                xr[k] = *reinterpret_cast<const float4*>(&x1base[(c0c + cl) * 4096 + pq * 4]);
                int j = i >> 3, cq = i & 7;
                wr[k] = *reinterpret_cast<const float4*>(&w_red[j * NC + c0c + cq * 4]);
            }
        }

        // compute over 32 channels of this chunk
#pragma unroll 4
        for (int cc = 0; cc < 32; cc++) {
            const float4 wa = *reinterpret_cast<const float4*>(&sm[A2_SW + cc * 68 + jg * 8]);
            const float4 wb = *reinterpret_cast<const float4*>(&sm[A2_SW + cc * 68 + jg * 8 + 4]);
            unsigned long long w2[8];
            w2[0] = pack2(wa.x); w2[1] = pack2(wa.y); w2[2] = pack2(wa.z); w2[3] = pack2(wa.w);
            w2[4] = pack2(wb.x); w2[5] = pack2(wb.y); w2[6] = pack2(wb.z); w2[7] = pack2(wb.w);
            const ulonglong2 xv = *reinterpret_cast<const ulonglong2*>(&sm[A2_SX + cc * 64 + pxg * 4]);
#pragma unroll
            for (int jj = 0; jj < 8; jj++) {
                fma2(acc[jj][0], w2[jj], xv.x);
                fma2(acc[jj][1], w2[jj], xv.y);
            }
        }
        __syncthreads();
    }

    // r = relu(acc + b_red) -> s_r (overlaps s_x/s_w)
#pragma unroll
    for (int jj = 0; jj < 8; jj++) {
        const int j = jg * 8 + jj;
        const float bj = sm[A2_BRD + j];
        float4 rv;
        rv.x = fmaxf(lo32(acc[jj][0]) + bj, 0.f);
        rv.y = fmaxf(hi32(acc[jj][0]) + bj, 0.f);
        rv.z = fmaxf(lo32(acc[jj][1]) + bj, 0.f);
        rv.w = fmaxf(hi32(acc[jj][1]) + bj, 0.f);
        *reinterpret_cast<float4*>(&sm[A2_SR + j * 64 + pxg * 4]) = rv;
    }
    __syncthreads();

    // span: kern[k][px] = b_span[k] + sum_j w_span[k][j] * r[j][px]
    if (tid < 64) {
        float kf[NKK];
#pragma unroll
        for (int k = 0; k < NKK; k++) kf[k] = sm[A2_BSP + k];
#pragma unroll 8
        for (int j = 0; j < NRED; j++) {
            const float rv = sm[A2_SR + j * 64 + tid];
#pragma unroll
            for (int k = 0; k < NKK; k++)
                kf[k] = fmaf(sm[A2_WSP + k * NRED + j], rv, kf[k]);
        }
#pragma unroll
        for (int k = 0; k < NKK; k++)
            g_kern[(b * NKK + k) * 4096 + pxin + tid] = kf[k];
    }
}

// ---------------------------------------------------------------------------
// Kernel B: fused involution + dwconv_out, channels PARALLEL in block.
// Block: 8 channels x (8h x 64w) output tile. Grid (8,32,8) = 2048 blocks.
// Only 2 barriers per block. kern tile held in registers across channels.
// ---------------------------------------------------------------------------
#define B_EH 10
#define B_EWP 68
#define B_ESZ (B_EH * B_EWP)      // 680
#define B_HH 12
#define B_HWP 72
#define B_HSZ (B_HH * B_HWP)      // 864
#define B_CPB 8

#define B_K  0                          // 9*680  = 6120
#define B_X  6120                       // 8*864  = 6912
#define B_Y  13032                      // 8*680  = 5440
#define B_WO 18472                      // 72
#define B_BO 18544                      // 8
#define B_SMEM_FLOATS 18552
#define B_SMEM_BYTES (B_SMEM_FLOATS * 4)  // 74208

__global__ __launch_bounds__(256)
void tm_B(const float* __restrict__ w_out, const float* __restrict__ b_out,
          float* __restrict__ out)
{
    extern __shared__ float sm[];
    const int tid = threadIdx.x;
    const int h0  = blockIdx.x * 8;
    const int cg0 = blockIdx.y * B_CPB;
    const int b   = blockIdx.z;

    // ---- phase 0: stage kern-ext, x1-halo, weights ----
    for (int i = tid; i < NKK * B_ESZ; i += 256) {
        int kk = i / B_ESZ, rem = i - kk * B_ESZ;
        int Ey = rem / B_EWP, Ex = rem - Ey * B_EWP;
        int gy = h0 - 1 + Ey, gx = Ex - 1;
        float v = 0.f;
        if (gy >= 0 && gy < NH && gx >= 0 && gx < NW)
            v = g_kern[(b * NKK + kk) * 4096 + gy * NW + gx];
        sm[B_K + i] = v;
    }
    for (int i = tid; i < B_CPB * B_HSZ; i += 256) {
        int cc = i / B_HSZ, rem = i - cc * B_HSZ;
        int r = rem / B_HWP, col = rem - r * B_HWP;
        int gy = h0 - 2 + r, gx = col - 2;
        float v = 0.f;
        if (gy >= 0 && gy < NH && gx >= 0 && gx < NW)
            v = g_x1[((long long)(b * NC + cg0 + cc)) * 4096 + gy * NW + gx];
        sm[B_X + i] = v;
    }
    if (tid < 72) sm[B_WO + tid] = w_out[cg0 * 9 + tid];
    if (tid < B_CPB) sm[B_BO + tid] = b_out[cg0 + tid];
    __syncthreads();

    // ---- phase 1: involution on extended tile; kern in regs, loop channels ----
    if (tid < 170) {
        const int Ey = tid / 17;
        const int Ex0 = (tid - Ey * 17) * 4;
        float4 kr[9];
#pragma unroll
        for (int t = 0; t < 9; t++)
            kr[t] = *reinterpret_cast<const float4*>(&sm[B_K + t * B_ESZ + Ey * B_EWP + Ex0]);
#pragma unroll
        for (int cc = 0; cc < B_CPB; cc++) {
            float y0 = 0.f, y1 = 0.f, y2 = 0.f, y3 = 0.f;
#pragma unroll
            for (int ki = 0; ki < 3; ki++) {
                const float4 xa = *reinterpret_cast<const float4*>(
                    &sm[B_X + cc * B_HSZ + (Ey + ki) * B_HWP + Ex0]);
                const float4 xb = *reinterpret_cast<const float4*>(
                    &sm[B_X + cc * B_HSZ + (Ey + ki) * B_HWP + Ex0 + 4]);
                const float a[8] = {xa.x, xa.y, xa.z, xa.w, xb.x, xb.y, xb.z, xb.w};
#pragma unroll
                for (int kj = 0; kj < 3; kj++) {
                    const float4 kv = kr[ki * 3 + kj];
                    y0 = fmaf(kv.x, a[kj + 0], y0);
                    y1 = fmaf(kv.y, a[kj + 1], y1);
                    y2 = fmaf(kv.z, a[kj + 2], y2);
                    y3 = fmaf(kv.w, a[kj + 3], y3);
                }
            }
            float4 st = {y0, y1, y2, y3};
            *reinterpret_cast<float4*>(&sm[B_Y + cc * B_ESZ + Ey * B_EWP + Ex0]) = st;
        }
    }
    __syncthreads();

    // ---- phase 2: dwconv_out from s_y, sliding 3-row window, 16 px/thread ----
    {
        const int cc = tid >> 5;
        const int lane = tid & 31;
        const int Oyg = lane >> 4;          // 0..1 -> ext row base Oyg*4
        const int Ox0 = (lane & 15) * 4;
        float wo[9];
#pragma unroll
        for (int k = 0; k < 9; k++) wo[k] = sm[B_WO + cc * 9 + k];
        const float bo = sm[B_BO + cc];

        const float* yb = &sm[B_Y + cc * B_ESZ];
        const int er0 = Oyg * 4;
        float4 r0a = *reinterpret_cast<const float4*>(&yb[(er0 + 0) * B_EWP + Ox0]);
        float4 r0b = *reinterpret_cast<const float4*>(&yb[(er0 + 0) * B_EWP + Ox0 + 4]);
        float4 r1a = *reinterpret_cast<const float4*>(&yb[(er0 + 1) * B_EWP + Ox0]);
        float4 r1b = *reinterpret_cast<const float4*>(&yb[(er0 + 1) * B_EWP + Ox0 + 4]);

        float* ob = &out[((long long)(b * NC + cg0 + cc)) * 4096 + (h0 + Oyg * 4) * NW + Ox0];
#pragma unroll
        for (int oy = 0; oy < 4; oy++) {
            const float4 r2a = *reinterpret_cast<const float4*>(&yb[(er0 + oy + 2) * B_EWP + Ox0]);
            const float4 r2b = *reinterpret_cast<const float4*>(&yb[(er0 + oy + 2) * B_EWP + Ox0 + 4]);
            float o0 = bo, o1 = bo, o2 = bo, o3 = bo;
            {
                const float a[8] = {r0a.x, r0a.y, r0a.z, r0a.w, r0b.x, r0b.y, r0b.z, r0b.w};
#pragma unroll
                for (int dj = 0; dj < 3; dj++) {
                    const float w = wo[dj];
                    o0 = fmaf(w, a[dj + 0], o0); o1 = fmaf(w, a[dj + 1], o1);
                    o2 = fmaf(w, a[dj + 2], o2); o3 = fmaf(w, a[dj + 3], o3);
                }
            }
            {
                const float a[8] = {r1a.x, r1a.y, r1a.z, r1a.w, r1b.x, r1b.y, r1b.z, r1b.w};
#pragma unroll
                for (int dj = 0; dj < 3; dj++) {
                    const float w = wo[3 + dj];
                    o0 = fmaf(w, a[dj + 0], o0); o1 = fmaf(w, a[dj + 1], o1);
                    o2 = fmaf(w, a[dj + 2], o2); o3 = fmaf(w, a[dj + 3], o3);
                }
            }
            {
                const float a[8] = {r2a.x, r2a.y, r2a.z, r2a.w, r2b.x, r2b.y, r2b.z, r2b.w};
#pragma unroll
                for (int dj = 0; dj < 3; dj++) {
                    const float w = wo[6 + dj];
                    o0 = fmaf(w, a[dj + 0], o0); o1 = fmaf(w, a[dj + 1], o1);
                    o2 = fmaf(w, a[dj + 2], o2); o3 = fmaf(w, a[dj + 3], o3);
                }
            }
            float4 st = {o0, o1, o2, o3};
            *reinterpret_cast<float4*>(&ob[oy * NW]) = st;
            r0a = r1a; r0b = r1b; r1a = r2a; r1b = r2b;
        }
    }
}

// ---------------------------------------------------------------------------
extern "C" void kernel_launch(void* const* d_in, const int* in_sizes, int n_in,
                              void* d_out, int out_size)
{
    (void)in_sizes; (void)n_in; (void)out_size;
    const float* x      = (const float*)d_in[0];
    const float* w_in   = (const float*)d_in[1];
    const float* b_in   = (const float*)d_in[2];
    const float* w_red  = (const float*)d_in[3];
    const float* b_red  = (const float*)d_in[4];
    const float* w_span = (const float*)d_in[5];
    const float* b_span = (const float*)d_in[6];
    const float* w_out  = (const float*)d_in[7];
    const float* b_out  = (const float*)d_in[8];
    float* out = (float*)d_out;

    cudaFuncSetAttribute(tm_B, cudaFuncAttributeMaxDynamicSharedMemorySize,
                         B_SMEM_BYTES);

    tm_A1<<<dim3(4, 256, 8), 256>>>(x, w_in, b_in);
    tm_A2<<<512, 128>>>(w_red, b_red, w_span, b_span);
    tm_B<<<dim3(8, 32, 8), 256, B_SMEM_BYTES>>>(w_out, b_out, out);
}

// round 8
// speedup vs baseline: 2.5976x; 1.1890x over previous
#include <cuda_runtime.h>

// Problem constants
#define NB 8
#define NC 256
#define NH 64
#define NW 64
#define NRED 64
#define NKK 9

// Scratch (device globals: allocation-free rule)
__device__ float g_x1[NB * NC * NH * NW];     // 32 MB: output of dwconv_in
__device__ float g_kern[NB * NKK * NH * NW];  // 1.125 MB: per-pixel 3x3 kernels

// ---------------------------------------------------------------------------
// Packed fp32x2 helpers (sm_103a)
// ---------------------------------------------------------------------------
__device__ __forceinline__ unsigned long long pack2(float v) {
    unsigned long long r;
    unsigned u = __float_as_uint(v);
    asm("mov.b64 %0, {%1, %1};" : "=l"(r) : "r"(u));
    return r;
}
__device__ __forceinline__ void fma2(unsigned long long& d,
                                     unsigned long long a,
                                     unsigned long long b) {
    asm("fma.rn.f32x2 %0, %1, %2, %0;" : "+l"(d) : "l"(a), "l"(b));
}
__device__ __forceinline__ float lo32(unsigned long long v) {
    return __uint_as_float((unsigned)(v & 0xffffffffu));
}
__device__ __forceinline__ float hi32(unsigned long long v) {
    return __uint_as_float((unsigned)(v >> 32));
}

// ---------------------------------------------------------------------------
// Kernel A1: dwconv_in (x -> g_x1). Tile 16h x 64w per (b,c). 8192 blocks.
// smem layout: image col c at offset c+4, stride 72. Aligned f4 everywhere.
// Left halo col (-1) at offset 3, right halo col (64) at offset 68: always 0.
// ---------------------------------------------------------------------------
#define A1_ST 72
#define A1_RS 18                 // halo rows (gy = h0-1 .. h0+16)

__global__ __launch_bounds__(256)
void tm_A1(const float* __restrict__ x,
           const float* __restrict__ w_in, const float* __restrict__ b_in)
{
    __shared__ float sh[A1_RS * A1_ST];
    const int tid = threadIdx.x;
    const int h0 = blockIdx.x * 16;
    const int c  = blockIdx.y;
    const int b  = blockIdx.z;

    const float* xc = x + (b * NC + c) * (NH * NW);

    // interior: 18 rows x 16 f4, aligned loads/stores, shift-only indexing
#pragma unroll
    for (int u = tid; u < 288; u += 256) {
        const int r = u >> 4, q = u & 15;
        const int gy = h0 - 1 + r;
        float4 v = {0.f, 0.f, 0.f, 0.f};
        if (gy >= 0 && gy < NH)
            v = *reinterpret_cast<const float4*>(&xc[gy * NW + q * 4]);
        *reinterpret_cast<float4*>(&sh[r * A1_ST + 4 + q * 4]) = v;
    }
    // halo columns are always outside the image -> zero
    if (tid < 36) {
        const int r = tid >> 1;
        sh[r * A1_ST + ((tid & 1) ? 68 : 3)] = 0.f;
    }
    float wv[9];
#pragma unroll
    for (int k = 0; k < 9; k++) wv[k] = __ldg(&w_in[c * 9 + k]);
    const float bias = __ldg(&b_in[c]);
    __syncthreads();

    const int Oy = tid >> 4;
    const int Ox0 = (tid & 15) * 4;
    float o0 = bias, o1 = bias, o2 = bias, o3 = bias;
#pragma unroll
    for (int di = 0; di < 3; di++) {
        const float* row = &sh[(Oy + di) * A1_ST];
        const float4 A  = *reinterpret_cast<const float4*>(&row[Ox0]);      // .w = col Ox0-1
        const float4 Bv = *reinterpret_cast<const float4*>(&row[Ox0 + 4]);  // cols Ox0..Ox0+3
        const float4 C  = *reinterpret_cast<const float4*>(&row[Ox0 + 8]);  // .x = col Ox0+4
        const float a[6] = {A.w, Bv.x, Bv.y, Bv.z, Bv.w, C.x};
#pragma unroll
        for (int dj = 0; dj < 3; dj++) {
            const float w = wv[di * 3 + dj];
            o0 = fmaf(w, a[dj + 0], o0);
            o1 = fmaf(w, a[dj + 1], o1);
            o2 = fmaf(w, a[dj + 2], o2);
            o3 = fmaf(w, a[dj + 3], o3);
        }
    }
    float4 st = {o0, o1, o2, o3};
    *reinterpret_cast<float4*>(&g_x1[(b * NC + c) * (NH * NW) + (h0 + Oy) * NW + Ox0]) = st;
}

// ---------------------------------------------------------------------------
// Kernel A2: reduce GEMM (64x256x32768) + relu + span (9x64) -> g_kern.
// 256 blocks x 128 threads. Block tile: 64j x 128px, c chunked by 32.
// Thread: 8j x 8px, f32x2 accumulators. Weights pre-duplicated as f32x2
// pairs in smem (no per-iteration packing movs).
// ---------------------------------------------------------------------------
#define A2_SX 0                   // s_x[32c][128px] = 4096 floats
#define A2_SW2 4096               // s_w2[32c][64j*2 + pad] stride 136 = 4352
#define A2_SR 0                   // s_r[64j][128px] = 8192 (overlaps SX+SW2)
#define A2_AUX 8448
#define A2_WSP (A2_AUX + 0)       // 576
#define A2_BSP (A2_AUX + 576)     // 9 (pad to 16)
#define A2_BRD (A2_AUX + 592)     // 64
#define A2_SMEM (A2_AUX + 656)    // 9104 floats = 36.4KB

__global__ __launch_bounds__(128)
void tm_A2(const float* __restrict__ w_red, const float* __restrict__ b_red,
           const float* __restrict__ w_span, const float* __restrict__ b_span)
{
    __shared__ float sm[A2_SMEM];
    const int tid = threadIdx.x;
    const int px0 = blockIdx.x * 128;
    const int b = px0 >> 12;
    const int pxin = px0 & 4095;

    // aux staging
    for (int i = tid; i < 656; i += 128) {
        if (i < 576)               sm[A2_AUX + i] = w_span[i];
        else if (i < 585)          sm[A2_AUX + i] = b_span[i - 576];
        else if (i >= 592)         sm[A2_AUX + i] = b_red[i - 592];
    }

    const int jg = tid >> 4;      // 0..7  (8 j per group)
    const int pxg = tid & 15;     // 0..15 (8 px per group)

    unsigned long long acc[8][4];
#pragma unroll
    for (int jj = 0; jj < 8; jj++)
#pragma unroll
        for (int q = 0; q < 4; q++) acc[jj][q] = 0ULL;

    const float* x1base = g_x1 + (long long)b * NC * 4096 + pxin;

    float4 xr[8], wr[4];
    // prefetch chunk 0
    {
#pragma unroll
        for (int k = 0; k < 8; k++) {
            int i = tid + k * 128;
            int cl = i >> 5, pq = i & 31;
            xr[k] = *reinterpret_cast<const float4*>(&x1base[cl * 4096 + pq * 4]);
        }
#pragma unroll
        for (int k = 0; k < 4; k++) {
            int i = tid + k * 128;
            int j = i >> 3, cq = i & 7;
            wr[k] = *reinterpret_cast<const float4*>(&w_red[j * NC + cq * 4]);
        }
    }

    for (int ch = 0; ch < 8; ch++) {
        // store staged chunk
#pragma unroll
        for (int k = 0; k < 8; k++) {
            int i = tid + k * 128;
            int cl = i >> 5, pq = i & 31;
            *reinterpret_cast<float4*>(&sm[A2_SX + cl * 128 + pq * 4]) = xr[k];
        }
#pragma unroll
        for (int k = 0; k < 4; k++) {
            int i = tid + k * 128;
            int j = i >> 3, cq = i & 7;
            *reinterpret_cast<unsigned long long*>(&sm[A2_SW2 + (cq * 4 + 0) * 136 + j * 2]) = pack2(wr[k].x);
            *reinterpret_cast<unsigned long long*>(&sm[A2_SW2 + (cq * 4 + 1) * 136 + j * 2]) = pack2(wr[k].y);
            *reinterpret_cast<unsigned long long*>(&sm[A2_SW2 + (cq * 4 + 2) * 136 + j * 2]) = pack2(wr[k].z);
            *reinterpret_cast<unsigned long long*>(&sm[A2_SW2 + (cq * 4 + 3) * 136 + j * 2]) = pack2(wr[k].w);
        }
        __syncthreads();

        if (ch + 1 < 8) {
            const int c0c = (ch + 1) * 32;
#pragma unroll
            for (int k = 0; k < 8; k++) {
                int i = tid + k * 128;
                int cl = i >> 5, pq = i & 31;
                xr[k] = *reinterpret_cast<const float4*>(&x1base[(c0c + cl) * 4096 + pq * 4]);
            }
#pragma unroll
            for (int k = 0; k < 4; k++) {
                int i = tid + k * 128;
                int j = i >> 3, cq = i & 7;
                wr[k] = *reinterpret_cast<const float4*>(&w_red[j * NC + c0c + cq * 4]);
            }
        }

        // compute over 32 channels of this chunk
#pragma unroll 4
        for (int cc = 0; cc < 32; cc++) {
            const float* wbp = &sm[A2_SW2 + cc * 136 + jg * 16];
            const ulonglong2 w01 = *reinterpret_cast<const ulonglong2*>(wbp);
            const ulonglong2 w23 = *reinterpret_cast<const ulonglong2*>(wbp + 4);
            const ulonglong2 w45 = *reinterpret_cast<const ulonglong2*>(wbp + 8);
            const ulonglong2 w67 = *reinterpret_cast<const ulonglong2*>(wbp + 12);
            const unsigned long long w2[8] = {w01.x, w01.y, w23.x, w23.y,
                                              w45.x, w45.y, w67.x, w67.y};
            const ulonglong2 xv0 = *reinterpret_cast<const ulonglong2*>(&sm[A2_SX + cc * 128 + pxg * 8]);
            const ulonglong2 xv1 = *reinterpret_cast<const ulonglong2*>(&sm[A2_SX + cc * 128 + pxg * 8 + 4]);
#pragma unroll
            for (int jj = 0; jj < 8; jj++) {
                fma2(acc[jj][0], w2[jj], xv0.x);
                fma2(acc[jj][1], w2[jj], xv0.y);
                fma2(acc[jj][2], w2[jj], xv1.x);
                fma2(acc[jj][3], w2[jj], xv1.y);
            }
        }
        __syncthreads();
    }

    // r = relu(acc + b_red) -> s_r (overlaps s_x/s_w2)
#pragma unroll
    for (int jj = 0; jj < 8; jj++) {
        const int j = jg * 8 + jj;
        const float bj = sm[A2_BRD + j];
        float4 ra, rb;
        ra.x = fmaxf(lo32(acc[jj][0]) + bj, 0.f);
        ra.y = fmaxf(hi32(acc[jj][0]) + bj, 0.f);
        ra.z = fmaxf(lo32(acc[jj][1]) + bj, 0.f);
        ra.w = fmaxf(hi32(acc[jj][1]) + bj, 0.f);
        rb.x = fmaxf(lo32(acc[jj][2]) + bj, 0.f);
        rb.y = fmaxf(hi32(acc[jj][2]) + bj, 0.f);
        rb.z = fmaxf(lo32(acc[jj][3]) + bj, 0.f);
        rb.w = fmaxf(hi32(acc[jj][3]) + bj, 0.f);
        *reinterpret_cast<float4*>(&sm[A2_SR + j * 128 + pxg * 8]) = ra;
        *reinterpret_cast<float4*>(&sm[A2_SR + j * 128 + pxg * 8 + 4]) = rb;
    }
    __syncthreads();

    // span: kern[k][px] = b_span[k] + sum_j w_span[k][j] * r[j][px]
    {
        float kf[NKK];
#pragma unroll
        for (int k = 0; k < NKK; k++) kf[k] = sm[A2_BSP + k];
#pragma unroll 8
        for (int j = 0; j < NRED; j++) {
            const float rv = sm[A2_SR + j * 128 + tid];
#pragma unroll
            for (int k = 0; k < NKK; k++)
                kf[k] = fmaf(sm[A2_WSP + k * NRED + j], rv, kf[k]);
        }
#pragma unroll
        for (int k = 0; k < NKK; k++)
            g_kern[(b * NKK + k) * 4096 + pxin + tid] = kf[k];
    }
}

// ---------------------------------------------------------------------------
// Kernel B: fused involution + dwconv_out, channels PARALLEL in block.
// Block: 8 channels x (8h x 64w) output tile. Grid (8,32,8) = 2048 blocks.
// x1 halo uses aligned layout (col c at offset c+4, stride 72); kern staged
// via aligned LDG.128 + scalar STS into the ext layout.
// ---------------------------------------------------------------------------
#define B_EH 10
#define B_EWP 68
#define B_ESZ (B_EH * B_EWP)      // 680
#define B_HH 12
#define B_HST 72
#define B_HSZ (B_HH * B_HST)      // 864
#define B_CPB 8

#define B_K  0                          // 9*680  = 6120
#define B_X  6120                       // 8*864  = 6912
#define B_Y  13032                      // 8*680  = 5440
#define B_WO 18472                      // 72
#define B_BO 18544                      // 8
#define B_SMEM_FLOATS 18552
#define B_SMEM_BYTES (B_SMEM_FLOATS * 4)  // 74208

__global__ __launch_bounds__(256)
void tm_B(const float* __restrict__ w_out, const float* __restrict__ b_out,
          float* __restrict__ out)
{
    extern __shared__ float sm[];
    const int tid = threadIdx.x;
    const int h0  = blockIdx.x * 8;
    const int cg0 = blockIdx.y * B_CPB;
    const int b   = blockIdx.z;

    // ---- phase 0a: kern ext tile. aligned LDG.128, scalar STS at +1 shift.
    // 9 planes x 10 rows x 16 f4 groups = 1440 units.
    for (int i = tid; i < 1440; i += 256) {
        const int kk = i / 160;
        const int rem = i - kk * 160;
        const int r = rem >> 4, g = rem & 15;
        const int gy = h0 - 1 + r;
        float4 v = {0.f, 0.f, 0.f, 0.f};
        if (gy >= 0 && gy < NH)
            v = *reinterpret_cast<const float4*>(&g_kern[(b * NKK + kk) * 4096 + gy * NW + g * 4]);
        float* dst = &sm[B_K + kk * B_ESZ + r * B_EWP + g * 4 + 1];
        dst[0] = v.x; dst[1] = v.y; dst[2] = v.z; dst[3] = v.w;
    }
    // ext col 0 (image col -1) and ext cols 65..67: zero. 9*10 = 90 rows.
    if (tid < 90) {
        const int kk = tid / 10, r = tid - kk * 10;
        float* rowp = &sm[B_K + kk * B_ESZ + r * B_EWP];
        rowp[0] = 0.f; rowp[65] = 0.f; rowp[66] = 0.f; rowp[67] = 0.f;
    }

    // ---- phase 0b: x1 halo, aligned f4, shift-only indexing ----
    {
        const int ccl = tid >> 5, lane = tid & 31;
        const float* xsrc = &g_x1[((long long)(b * NC + cg0 + ccl)) * 4096];
        float* xdst = &sm[B_X + ccl * B_HSZ];
#pragma unroll
        for (int k = 0; k < 6; k++) {
            const int u = lane + 32 * k;     // 0..191: 12 rows x 16 f4
            const int r = u >> 4, g = u & 15;
            const int gy = h0 - 2 + r;
            float4 v = {0.f, 0.f, 0.f, 0.f};
            if (gy >= 0 && gy < NH)
                v = *reinterpret_cast<const float4*>(&xsrc[gy * NW + g * 4]);
            *reinterpret_cast<float4*>(&xdst[r * B_HST + 4 + g * 4]) = v;
        }
    }
    // edge cols (-2,-1,64,65) always outside image -> zero. 8cc x 12 rows.
    if (tid < 96) {
        const int cc2 = tid / 12, r = tid - cc2 * 12;
        float* p = &sm[B_X + cc2 * B_HSZ + r * B_HST];
        p[2] = 0.f; p[3] = 0.f; p[68] = 0.f; p[69] = 0.f;
    }
    if (tid < 72) sm[B_WO + tid] = w_out[cg0 * 9 + tid];
    if (tid < B_CPB) sm[B_BO + tid] = b_out[cg0 + tid];
    __syncthreads();

    // ---- phase 1: involution on extended tile; kern in regs, loop channels ----
    if (tid < 170) {
        const int Ey = tid / 17;
        const int Ex0 = (tid - Ey * 17) * 4;
        float4 kr[9];
#pragma unroll
        for (int t = 0; t < 9; t++)
            kr[t] = *reinterpret_cast<const float4*>(&sm[B_K + t * B_ESZ + Ey * B_EWP + Ex0]);
#pragma unroll
        for (int cc = 0; cc < B_CPB; cc++) {
            float y0 = 0.f, y1 = 0.f, y2 = 0.f, y3 = 0.f;
#pragma unroll
            for (int ki = 0; ki < 3; ki++) {
                const float* xrow = &sm[B_X + cc * B_HSZ + (Ey + ki) * B_HST];
                const float4 A  = *reinterpret_cast<const float4*>(&xrow[Ex0]);     // .z,.w = cols Ex0-2,Ex0-1
                const float4 Bv = *reinterpret_cast<const float4*>(&xrow[Ex0 + 4]); // cols Ex0..Ex0+3
                const float a[6] = {A.z, A.w, Bv.x, Bv.y, Bv.z, Bv.w};
#pragma unroll
                for (int kj = 0; kj < 3; kj++) {
                    const float4 kv = kr[ki * 3 + kj];
                    y0 = fmaf(kv.x, a[kj + 0], y0);
                    y1 = fmaf(kv.y, a[kj + 1], y1);
                    y2 = fmaf(kv.z, a[kj + 2], y2);
                    y3 = fmaf(kv.w, a[kj + 3], y3);
                }
            }
            float4 st = {y0, y1, y2, y3};
            *reinterpret_cast<float4*>(&sm[B_Y + cc * B_ESZ + Ey * B_EWP + Ex0]) = st;
        }
    }
    __syncthreads();

    // ---- phase 2: dwconv_out from s_y, sliding 3-row window, 16 px/thread ----
    {
        const int cc = tid >> 5;
        const int lane = tid & 31;
        const int Oyg = lane >> 4;          // 0..1 -> ext row base Oyg*4
        const int Ox0 = (lane & 15) * 4;
        float wo[9];
#pragma unroll
        for (int k = 0; k < 9; k++) wo[k] = sm[B_WO + cc * 9 + k];
        const float bo = sm[B_BO + cc];

        const float* yb = &sm[B_Y + cc * B_ESZ];
        const int er0 = Oyg * 4;
        float4 r0a = *reinterpret_cast<const float4*>(&yb[(er0 + 0) * B_EWP + Ox0]);
        float4 r0b = *reinterpret_cast<const float4*>(&yb[(er0 + 0) * B_EWP + Ox0 + 4]);
        float4 r1a = *reinterpret_cast<const float4*>(&yb[(er0 + 1) * B_EWP + Ox0]);
        float4 r1b = *reinterpret_cast<const float4*>(&yb[(er0 + 1) * B_EWP + Ox0 + 4]);

        float* ob = &out[((long long)(b * NC + cg0 + cc)) * 4096 + (h0 + Oyg * 4) * NW + Ox0];
#pragma unroll
        for (int oy = 0; oy < 4; oy++) {
            const float4 r2a = *reinterpret_cast<const float4*>(&yb[(er0 + oy + 2) * B_EWP + Ox0]);
            const float4 r2b = *reinterpret_cast<const float4*>(&yb[(er0 + oy + 2) * B_EWP + Ox0 + 4]);
            float o0 = bo, o1 = bo, o2 = bo, o3 = bo;
            {
                const float a[8] = {r0a.x, r0a.y, r0a.z, r0a.w, r0b.x, r0b.y, r0b.z, r0b.w};
#pragma unroll
                for (int dj = 0; dj < 3; dj++) {
                    const float w = wo[dj];
                    o0 = fmaf(w, a[dj + 0], o0); o1 = fmaf(w, a[dj + 1], o1);
                    o2 = fmaf(w, a[dj + 2], o2); o3 = fmaf(w, a[dj + 3], o3);
                }
            }
            {
                const float a[8] = {r1a.x, r1a.y, r1a.z, r1a.w, r1b.x, r1b.y, r1b.z, r1b.w};
#pragma unroll
                for (int dj = 0; dj < 3; dj++) {
                    const float w = wo[3 + dj];
                    o0 = fmaf(w, a[dj + 0], o0); o1 = fmaf(w, a[dj + 1], o1);
                    o2 = fmaf(w, a[dj + 2], o2); o3 = fmaf(w, a[dj + 3], o3);
                }
            }
            {
                const float a[8] = {r2a.x, r2a.y, r2a.z, r2a.w, r2b.x, r2b.y, r2b.z, r2b.w};
#pragma unroll
                for (int dj = 0; dj < 3; dj++) {
                    const float w = wo[6 + dj];
                    o0 = fmaf(w, a[dj + 0], o0); o1 = fmaf(w, a[dj + 1], o1);
                    o2 = fmaf(w, a[dj + 2], o2); o3 = fmaf(w, a[dj + 3], o3);
                }
            }
            float4 st = {o0, o1, o2, o3};
            *reinterpret_cast<float4*>(&ob[oy * NW]) = st;
            r0a = r1a; r0b = r1b; r1a = r2a; r1b = r2b;
        }
    }
}

// ---------------------------------------------------------------------------
extern "C" void kernel_launch(void* const* d_in, const int* in_sizes, int n_in,
                              void* d_out, int out_size)
{
    (void)in_sizes; (void)n_in; (void)out_size;
    const float* x      = (const float*)d_in[0];
    const float* w_in   = (const float*)d_in[1];
    const float* b_in   = (const float*)d_in[2];
    const float* w_red  = (const float*)d_in[3];
    const float* b_red  = (const float*)d_in[4];
    const float* w_span = (const float*)d_in[5];
    const float* b_span = (const float*)d_in[6];
    const float* w_out  = (const float*)d_in[7];
    const float* b_out  = (const float*)d_in[8];
    float* out = (float*)d_out;

    cudaFuncSetAttribute(tm_B, cudaFuncAttributeMaxDynamicSharedMemorySize,
                         B_SMEM_BYTES);

    tm_A1<<<dim3(4, 256, 8), 256>>>(x, w_in, b_in);
    tm_A2<<<256, 128>>>(w_red, b_red, w_span, b_span);
    tm_B<<<dim3(8, 32, 8), 256, B_SMEM_BYTES>>>(w_out, b_out, out);
}